// round 2
// baseline (speedup 1.0000x reference)
#include <cuda_runtime.h>

// MaskedConv2D: out = (conv3x3(x, w) + bias) * (maxpool3x3(|mask|) > 0)
// B=8, CIN=COUT=64, H=W=256, K=3, PAD=1, all fp32.

#define BB   8
#define CC   64
#define HH   256
#define WW   256

#define TH   8      // output rows per block
#define TW   32     // output cols per block
#define CI_T 16     // cin chunk
#define XROWS (TH + 2)
#define XCOLS (TW + 2)
#define XSTR  36    // padded smem row stride (floats), 144B = 16B-aligned rows

#define SW_FLOATS (9 * CI_T * 64)          // 9216
#define SX_FLOATS (CI_T * XROWS * XSTR)    // 5760
#define SM_FLOATS (XROWS * XSTR)           // 360
#define SMEM_BYTES ((SW_FLOATS + SX_FLOATS + SM_FLOATS) * 4)  // 61344

__device__ __forceinline__ unsigned long long pack2(float x, float y) {
    unsigned long long r;
    asm("mov.b64 %0, {%1, %2};" : "=l"(r) : "f"(x), "f"(y));
    return r;
}
__device__ __forceinline__ void fma2(unsigned long long& d,
                                     unsigned long long a,
                                     unsigned long long b) {
    asm("fma.rn.f32x2 %0, %1, %2, %0;" : "+l"(d) : "l"(a), "l"(b));
}
__device__ __forceinline__ float lo32(unsigned long long v) {
    return __uint_as_float((unsigned int)(v & 0xffffffffull));
}
__device__ __forceinline__ float hi32(unsigned long long v) {
    return __uint_as_float((unsigned int)(v >> 32));
}

__global__ __launch_bounds__(256, 2)
void masked_conv2d_kernel(const float* __restrict__ x,
                          const float* __restrict__ mask,
                          const float* __restrict__ w,
                          const float* __restrict__ bias,
                          float* __restrict__ out) {
    extern __shared__ float smem[];
    float* sw = smem;                       // [9][CI_T][64]  weights chunk
    float* sx = sw + SW_FLOATS;             // [CI_T][XROWS][XSTR] input halo tile
    float* sm = sx + SX_FLOATS;             // [XROWS][XSTR] mask tile

    const int tid = threadIdx.x;
    const int b  = blockIdx.z;
    const int h0 = blockIdx.y * TH;
    const int w0 = blockIdx.x * TW;

    // thread -> (cout group, pixel group). Warp-uniform cout group so weight
    // LDS is a broadcast (conflict-free, N=1).
    const int cg  = tid >> 6;         // 0..3
    const int pg  = tid & 63;         // 0..63
    const int lh  = pg >> 3;          // 0..7  (output row within tile)
    const int lw  = (pg & 7) * 4;     // 0,4,...,28 (output col within tile)
    const int cob = cg * 16;          // base cout of this thread's 16 channels

    // ---- mask halo tile (loaded once; region never overwritten) ----
    for (int i = tid; i < XROWS * XCOLS; i += 256) {
        int r = i / XCOLS, c = i - r * XCOLS;
        int gh = h0 - 1 + r, gw = w0 - 1 + c;
        float v = 0.f;
        if (gh >= 0 && gh < HH && gw >= 0 && gw < WW)
            v = mask[(b * HH + gh) * WW + gw];
        sm[r * XSTR + c] = v;
    }

    // ---- accumulators: 4 pixels x 8 f32x2 (= 16 couts), init with bias ----
    unsigned long long acc[4][8];
#pragma unroll
    for (int j = 0; j < 8; j++) {
        unsigned long long bj = pack2(bias[cob + 2 * j], bias[cob + 2 * j + 1]);
        acc[0][j] = bj; acc[1][j] = bj; acc[2][j] = bj; acc[3][j] = bj;
    }

    for (int cc2 = 0; cc2 < CC; cc2 += CI_T) {
        __syncthreads();  // previous chunk's compute must finish before reload

        // weights chunk: global [co][ci][kk] -> smem [kk][ci][co]
        for (int i = tid; i < SW_FLOATS; i += 256) {
            int co  = i / (CI_T * 9);
            int rem = i - co * (CI_T * 9);
            int ci  = rem / 9;
            int kk  = rem - ci * 9;
            sw[(kk * CI_T + ci) * 64 + co] = w[co * (CC * 9) + (cc2 + ci) * 9 + kk];
        }
        // x halo chunk (zero-filled out of bounds = conv zero padding)
        for (int i = tid; i < CI_T * XROWS * XCOLS; i += 256) {
            int ci  = i / (XROWS * XCOLS);
            int rem = i - ci * (XROWS * XCOLS);
            int r   = rem / XCOLS;
            int c   = rem - r * XCOLS;
            int gh = h0 - 1 + r, gw = w0 - 1 + c;
            float v = 0.f;
            if (gh >= 0 && gh < HH && gw >= 0 && gw < WW)
                v = x[((b * CC + cc2 + ci) * HH + gh) * WW + gw];
            sx[(ci * XROWS + r) * XSTR + c] = v;
        }
        __syncthreads();

#pragma unroll 2
        for (int ci = 0; ci < CI_T; ci++) {
            const float* xb = sx + (ci * XROWS + lh) * XSTR + lw;
#pragma unroll
            for (int kh = 0; kh < 3; kh++) {
                // 8 input values covering cols lw..lw+5 (+2 spare), 16B-aligned
                float4 a0 = *(const float4*)(xb + kh * XSTR);
                float4 a1 = *(const float4*)(xb + kh * XSTR + 4);
                float xv[8] = {a0.x, a0.y, a0.z, a0.w, a1.x, a1.y, a1.z, a1.w};
#pragma unroll
                for (int kw = 0; kw < 3; kw++) {
                    unsigned long long pk0 = pack2(xv[kw + 0], xv[kw + 0]);
                    unsigned long long pk1 = pack2(xv[kw + 1], xv[kw + 1]);
                    unsigned long long pk2 = pack2(xv[kw + 2], xv[kw + 2]);
                    unsigned long long pk3 = pack2(xv[kw + 3], xv[kw + 3]);
                    const ulonglong2* wp = (const ulonglong2*)
                        (sw + ((kh * 3 + kw) * CI_T + ci) * 64 + cob);
#pragma unroll
                    for (int q = 0; q < 4; q++) {
                        ulonglong2 wq2 = wp[q];   // 4 weights = 2 f32x2, broadcast LDS
                        fma2(acc[0][2 * q + 0], pk0, wq2.x);
                        fma2(acc[1][2 * q + 0], pk1, wq2.x);
                        fma2(acc[2][2 * q + 0], pk2, wq2.x);
                        fma2(acc[3][2 * q + 0], pk3, wq2.x);
                        fma2(acc[0][2 * q + 1], pk0, wq2.y);
                        fma2(acc[1][2 * q + 1], pk1, wq2.y);
                        fma2(acc[2][2 * q + 1], pk2, wq2.y);
                        fma2(acc[3][2 * q + 1], pk3, wq2.y);
                    }
                }
            }
        }
    }

    // ---- validity: 3x3 max-pool of mask tile per pixel ----
    float cm[6];
#pragma unroll
    for (int c = 0; c < 6; c++) {
        float m = 0.f;
#pragma unroll
        for (int dh = 0; dh < 3; dh++)
            m = fmaxf(m, sm[(lh + dh) * XSTR + lw + c]);
        cm[c] = m;
    }
    float vp[4];
#pragma unroll
    for (int p = 0; p < 4; p++) {
        float m = fmaxf(cm[p], fmaxf(cm[p + 1], cm[p + 2]));
        vp[p] = (m > 0.f) ? 1.f : 0.f;
    }

    const int gh = h0 + lh;
    const int gw = w0 + lw;
#pragma unroll
    for (int j = 0; j < 8; j++) {
        float4 vlo = make_float4(lo32(acc[0][j]) * vp[0], lo32(acc[1][j]) * vp[1],
                                 lo32(acc[2][j]) * vp[2], lo32(acc[3][j]) * vp[3]);
        float4 vhi = make_float4(hi32(acc[0][j]) * vp[0], hi32(acc[1][j]) * vp[1],
                                 hi32(acc[2][j]) * vp[2], hi32(acc[3][j]) * vp[3]);
        float* o0 = out + (((size_t)(b * CC + cob + 2 * j) * HH + gh) * WW + gw);
        float* o1 = o0 + (size_t)HH * WW;
        *(float4*)o0 = vlo;
        *(float4*)o1 = vhi;
    }
}

extern "C" void kernel_launch(void* const* d_in, const int* in_sizes, int n_in,
                              void* d_out, int out_size) {
    const float* x    = (const float*)d_in[0];
    const float* mask = (const float*)d_in[1];
    const float* w    = (const float*)d_in[2];
    const float* bias = (const float*)d_in[3];
    float* out = (float*)d_out;

    cudaFuncSetAttribute(masked_conv2d_kernel,
                         cudaFuncAttributeMaxDynamicSharedMemorySize, SMEM_BYTES);

    dim3 grid(WW / TW, HH / TH, BB);   // (8, 32, 8)
    masked_conv2d_kernel<<<grid, 256, SMEM_BYTES>>>(x, mask, w, bias, out);
}

// round 4
// speedup vs baseline: 1.2168x; 1.2168x over previous
#include <cuda_runtime.h>

// MaskedConv2D: out = (conv3x3(x, w) + bias) * (maxpool3x3(mask) > 0)
// B=8, CIN=COUT=64, H=W=256, K=3, PAD=1, fp32.
// fp32x2 (FFMA2) compute, cp.async double-buffered cin chunks.

#define BB   8
#define CC   64
#define HH   256
#define WW   256

#define TH   8       // output rows per block
#define TW   32      // output cols per block
#define CI_T 8       // cin chunk
#define NCHUNK (CC / CI_T)   // 8
#define XROWS (TH + 2)
#define XCOLS (TW + 2)
#define XSTR  36     // padded smem row stride (floats)

#define SWB (9 * CI_T * 64)          // 4608 floats per weight buffer
#define SXB (CI_T * XROWS * XSTR)    // 2880 floats per x buffer
#define SMB (XROWS * XSTR)           // 360 floats mask tile
#define SMEM_FLOATS (2 * SWB + 2 * SXB + SMB)           // 15336
#define SMEM_BYTES  (SMEM_FLOATS * 4)                   // 61344

// Pre-transposed weights: [chunk][kk][ci][co], 64*64*9 floats
__device__ float g_wtrans[CC * CC * 9];

__global__ void wtrans_kernel(const float* __restrict__ w) {
    int t = blockIdx.x * blockDim.x + threadIdx.x;
    if (t >= CC * CC * 9) return;
    int co = t & 63;
    int r  = t >> 6;            // (chunk*9+kk)*CI_T + ci
    int ci = r & (CI_T - 1);
    int r2 = r >> 3;            // chunk*9 + kk
    int kk = r2 % 9;
    int ch = r2 / 9;
    int ci_g = ch * CI_T + ci;
    g_wtrans[t] = w[co * (CC * 9) + ci_g * 9 + kk];
}

__device__ __forceinline__ unsigned long long pack2(float x, float y) {
    unsigned long long r;
    asm("mov.b64 %0, {%1, %2};" : "=l"(r) : "f"(x), "f"(y));
    return r;
}
__device__ __forceinline__ void fma2(unsigned long long& d,
                                     unsigned long long a,
                                     unsigned long long b) {
    asm("fma.rn.f32x2 %0, %1, %2, %0;" : "+l"(d) : "l"(a), "l"(b));
}
__device__ __forceinline__ float lo32(unsigned long long v) {
    return __uint_as_float((unsigned int)(v & 0xffffffffull));
}
__device__ __forceinline__ float hi32(unsigned long long v) {
    return __uint_as_float((unsigned int)(v >> 32));
}
__device__ __forceinline__ void cpa4(unsigned smem, const float* g) {
    asm volatile("cp.async.ca.shared.global [%0], [%1], 4;"
                 :: "r"(smem), "l"(g));
}
__device__ __forceinline__ void cpa16(unsigned smem, const float* g) {
    asm volatile("cp.async.cg.shared.global [%0], [%1], 16;"
                 :: "r"(smem), "l"(g));
}

__global__ __launch_bounds__(256, 2)
void masked_conv2d_kernel(const float* __restrict__ x,
                          const float* __restrict__ mask,
                          const float* __restrict__ bias,
                          float* __restrict__ out) {
    extern __shared__ float smem[];
    float* swb[2] = { smem, smem + SWB };
    float* sxb[2] = { smem + 2 * SWB, smem + 2 * SWB + SXB };
    float* sm = smem + 2 * SWB + 2 * SXB;

    const int tid = threadIdx.x;
    const int b  = blockIdx.z;
    const int h0 = blockIdx.y * TH;
    const int w0 = blockIdx.x * TW;

    const int cg  = tid >> 6;         // 0..3 cout group (warp-uniform)
    const int pg  = tid & 63;
    const int lh  = pg >> 3;          // 0..7
    const int lw  = (pg & 7) * 4;     // 0,4,..,28
    const int cob = cg * 16;

    const unsigned smem_base = (unsigned)__cvta_generic_to_shared(smem);
    const unsigned swb_a[2] = { smem_base, smem_base + SWB * 4 };
    const unsigned sxb_a[2] = { smem_base + 2 * SWB * 4,
                                smem_base + (2 * SWB + SXB) * 4 };

    // ---- pre-zero both x buffers (halo cells stay 0 forever) ----
    for (int i = tid; i < 2 * SXB; i += 256)
        sxb[0][i] = 0.f;

    // ---- mask halo tile ----
    for (int i = tid; i < XROWS * XCOLS; i += 256) {
        int r = i / XCOLS, c = i - r * XCOLS;
        int gh = h0 - 1 + r, gw = w0 - 1 + c;
        float v = 0.f;
        if (gh >= 0 && gh < HH && gw >= 0 && gw < WW)
            v = mask[(b * HH + gh) * WW + gw];
        sm[r * XSTR + c] = v;
    }
    __syncthreads();   // zeros + mask visible before any cp.async writes

    // ---- chunk loader: cp.async into buffer bi ----
    auto issue_chunk = [&](int ch, int bi) {
        // weights: linear stream from pre-transposed layout
        const float* wsrc = g_wtrans + ch * SWB;
        unsigned wdst = swb_a[bi];
#pragma unroll
        for (int k = 0; k < 5; k++) {
            int i = tid + k * 256;
            if (i < SWB / 4)
                cpa16(wdst + i * 16, wsrc + i * 4);
        }
        // x halo chunk: 4B per element, skip out-of-bounds (cells pre-zeroed)
        for (int i = tid; i < CI_T * XROWS * XCOLS; i += 256) {
            int ci  = i / (XROWS * XCOLS);
            int rem = i - ci * (XROWS * XCOLS);
            int r   = rem / XCOLS;
            int c   = rem - r * XCOLS;
            int gh = h0 - 1 + r, gw = w0 - 1 + c;
            if (gh >= 0 && gh < HH && gw >= 0 && gw < WW)
                cpa4(sxb_a[bi] + ((ci * XROWS + r) * XSTR + c) * 4,
                     x + ((size_t)(b * CC + ch * CI_T + ci) * HH + gh) * WW + gw);
        }
        asm volatile("cp.async.commit_group;");
    };

    // ---- accumulators: 4 pixels x 8 f32x2 (16 couts), init with bias ----
    unsigned long long acc[4][8];
    {
        const float4* bp = (const float4*)(bias + cob);
#pragma unroll
        for (int q = 0; q < 4; q++) {
            float4 bv = bp[q];
            unsigned long long b0 = pack2(bv.x, bv.y);
            unsigned long long b1 = pack2(bv.z, bv.w);
#pragma unroll
            for (int p = 0; p < 4; p++) {
                acc[p][2 * q + 0] = b0;
                acc[p][2 * q + 1] = b1;
            }
        }
    }

    issue_chunk(0, 0);

    for (int ch = 0; ch < NCHUNK; ch++) {
        const int bi = ch & 1;
        if (ch + 1 < NCHUNK) {
            issue_chunk(ch + 1, bi ^ 1);
            asm volatile("cp.async.wait_group 1;");
        } else {
            asm volatile("cp.async.wait_group 0;");
        }
        __syncthreads();   // chunk ch data visible to all

        const float* sw = swb[bi];
        const float* sx = sxb[bi];

#pragma unroll 2
        for (int ci = 0; ci < CI_T; ci++) {
            const float* xb = sx + (ci * XROWS + lh) * XSTR + lw;
#pragma unroll
            for (int kh = 0; kh < 3; kh++) {
                float4 a0 = *(const float4*)(xb + kh * XSTR);
                float2 a1 = *(const float2*)(xb + kh * XSTR + 4);
                // pack once per kh: pk[i] = {xv[i], xv[i]}
                unsigned long long pk[6];
                pk[0] = pack2(a0.x, a0.x);
                pk[1] = pack2(a0.y, a0.y);
                pk[2] = pack2(a0.z, a0.z);
                pk[3] = pack2(a0.w, a0.w);
                pk[4] = pack2(a1.x, a1.x);
                pk[5] = pack2(a1.y, a1.y);
#pragma unroll
                for (int kw = 0; kw < 3; kw++) {
                    const ulonglong2* wp = (const ulonglong2*)
                        (sw + ((kh * 3 + kw) * CI_T + ci) * 64 + cob);
#pragma unroll
                    for (int q = 0; q < 4; q++) {
                        ulonglong2 wq2 = wp[q];   // broadcast LDS.128
                        fma2(acc[0][2 * q + 0], pk[kw + 0], wq2.x);
                        fma2(acc[1][2 * q + 0], pk[kw + 1], wq2.x);
                        fma2(acc[2][2 * q + 0], pk[kw + 2], wq2.x);
                        fma2(acc[3][2 * q + 0], pk[kw + 3], wq2.x);
                        fma2(acc[0][2 * q + 1], pk[kw + 0], wq2.y);
                        fma2(acc[1][2 * q + 1], pk[kw + 1], wq2.y);
                        fma2(acc[2][2 * q + 1], pk[kw + 2], wq2.y);
                        fma2(acc[3][2 * q + 1], pk[kw + 3], wq2.y);
                    }
                }
            }
        }
        __syncthreads();   // all done with buffer bi before it is refilled
    }

    // ---- validity: 3x3 max-pool of mask tile per pixel ----
    float cm[6];
#pragma unroll
    for (int c = 0; c < 6; c++) {
        float m = 0.f;
#pragma unroll
        for (int dh = 0; dh < 3; dh++)
            m = fmaxf(m, sm[(lh + dh) * XSTR + lw + c]);
        cm[c] = m;
    }
    float vp[4];
#pragma unroll
    for (int p = 0; p < 4; p++) {
        float m = fmaxf(cm[p], fmaxf(cm[p + 1], cm[p + 2]));
        vp[p] = (m > 0.f) ? 1.f : 0.f;
    }

    const int gh = h0 + lh;
    const int gw = w0 + lw;
#pragma unroll
    for (int j = 0; j < 8; j++) {
        float4 vlo = make_float4(lo32(acc[0][j]) * vp[0], lo32(acc[1][j]) * vp[1],
                                 lo32(acc[2][j]) * vp[2], lo32(acc[3][j]) * vp[3]);
        float4 vhi = make_float4(hi32(acc[0][j]) * vp[0], hi32(acc[1][j]) * vp[1],
                                 hi32(acc[2][j]) * vp[2], hi32(acc[3][j]) * vp[3]);
        float* o0 = out + (((size_t)(b * CC + cob + 2 * j) * HH + gh) * WW + gw);
        float* o1 = o0 + (size_t)HH * WW;
        *(float4*)o0 = vlo;
        *(float4*)o1 = vhi;
    }
}

extern "C" void kernel_launch(void* const* d_in, const int* in_sizes, int n_in,
                              void* d_out, int out_size) {
    const float* x    = (const float*)d_in[0];
    const float* mask = (const float*)d_in[1];
    const float* w    = (const float*)d_in[2];
    const float* bias = (const float*)d_in[3];
    float* out = (float*)d_out;

    wtrans_kernel<<<(CC * CC * 9 + 255) / 256, 256>>>(w);

    cudaFuncSetAttribute(masked_conv2d_kernel,
                         cudaFuncAttributeMaxDynamicSharedMemorySize, SMEM_BYTES);
    dim3 grid(WW / TW, HH / TH, BB);   // (8, 32, 8)
    masked_conv2d_kernel<<<grid, 256, SMEM_BYTES>>>(x, mask, bias, out);
}